// round 3
// baseline (speedup 1.0000x reference)
#include <cuda_runtime.h>
#include <cuda_fp16.h>
#include <cstdint>

#define NN      8192
#define IND     256
#define OUTD    128
#define BNG     144            // 128 num cols + 1 denom + 15 pad
#define NCHUNK  (NN / 64)      // 128 K-chunks of 64

// ---------------- scratch ----------------
__device__ float  g_h[NN * OUTD];      // projected features fp32
__device__ __half g_whT[BNG * NN];     // B matrix [n][k] K-major fp16

// ---------------- helpers ----------------
__device__ __forceinline__ uint32_t smem_u32(const void* p) {
    uint32_t r;
    asm("{ .reg .u64 t; cvta.to.shared.u64 t, %1; cvt.u32.u64 %0, t; }" : "=r"(r) : "l"(p));
    return r;
}
__device__ __forceinline__ void cp_async16(uint32_t dst, const void* src) {
    asm volatile("cp.async.cg.shared.global [%0], [%1], 16;" :: "r"(dst), "l"(src) : "memory");
}
__device__ __forceinline__ int4 ldg_cs(const int4* p) {
    int4 v;
    asm volatile("ld.global.cs.v4.b32 {%0,%1,%2,%3}, [%4];"
                 : "=r"(v.x), "=r"(v.y), "=r"(v.z), "=r"(v.w) : "l"(p));
    return v;
}
__device__ __forceinline__ uint32_t lds32(uint32_t a) {
    uint32_t v;
    asm volatile("ld.shared.b32 %0, [%1];" : "=r"(v) : "r"(a));
    return v;
}
__device__ __forceinline__ void sts128(uint32_t a, uint32_t x, uint32_t y, uint32_t z, uint32_t w) {
    asm volatile("st.shared.v4.b32 [%0], {%1,%2,%3,%4};" :: "r"(a), "r"(x), "r"(y), "r"(z), "r"(w) : "memory");
}
__device__ __forceinline__ void mma16816(float* d, const uint32_t* a, const uint32_t* b) {
    asm volatile(
        "mma.sync.aligned.m16n8k16.row.col.f32.f16.f16.f32 "
        "{%0,%1,%2,%3}, {%4,%5,%6,%7}, {%8,%9}, {%0,%1,%2,%3};"
        : "+f"(d[0]), "+f"(d[1]), "+f"(d[2]), "+f"(d[3])
        : "r"(a[0]), "r"(a[1]), "r"(a[2]), "r"(a[3]), "r"(b[0]), "r"(b[1]));
}
#define FMA2(d, a, b, c) asm("fma.rn.f32x2 %0, %1, %2, %3;" : "=l"(d) : "l"(a), "l"(b), "l"(c))
#define ADD2(d, a, b)    asm("add.rn.f32x2 %0, %1, %2;" : "=l"(d) : "l"(a), "l"(b))

// ================= K1: h = features @ W + b (fp32, f32x2 FMA) =================
__global__ void __launch_bounds__(256) proj_kernel(const float* __restrict__ feat,
                                                   const float* __restrict__ W,
                                                   const float* __restrict__ bias) {
    __shared__ __align__(16) float As[16][65];
    __shared__ __align__(16) float Bs[16][128];
    __shared__ __align__(16) float bsh[128];
    const int tid = threadIdx.x;
    const int tx = tid & 15, ty = tid >> 4;
    const int m0 = blockIdx.x * 64;

    if (tid < 128) bsh[tid] = bias[tid];

    unsigned long long acc[4][4];
#pragma unroll
    for (int i = 0; i < 4; i++)
#pragma unroll
        for (int j = 0; j < 4; j++) acc[i][j] = 0ull;

    for (int k0 = 0; k0 < IND; k0 += 16) {
        {
            int r = tid >> 2, cq = tid & 3;
            float4 f = *(const float4*)(feat + (size_t)(m0 + r) * IND + k0 + cq * 4);
            As[cq * 4 + 0][r] = f.x;
            As[cq * 4 + 1][r] = f.y;
            As[cq * 4 + 2][r] = f.z;
            As[cq * 4 + 3][r] = f.w;
#pragma unroll
            for (int it = 0; it < 2; it++) {
                int t2 = tid + it * 256;
                int kk = t2 >> 5, c4 = t2 & 31;
                *(float4*)&Bs[kk][c4 * 4] = *(const float4*)(W + (size_t)(k0 + kk) * OUTD + c4 * 4);
            }
        }
        __syncthreads();
#pragma unroll
        for (int k = 0; k < 16; k++) {
            unsigned long long bb[4];
#pragma unroll
            for (int j = 0; j < 4; j++)
                bb[j] = *(const unsigned long long*)&Bs[k][tx * 8 + 2 * j];
#pragma unroll
            for (int i = 0; i < 4; i++) {
                float a = As[k][ty * 4 + i];
                unsigned long long aa;
                asm("mov.b64 %0, {%1, %1};" : "=l"(aa) : "r"(__float_as_uint(a)));
#pragma unroll
                for (int j = 0; j < 4; j++) FMA2(acc[i][j], aa, bb[j], acc[i][j]);
            }
        }
        __syncthreads();
    }
#pragma unroll
    for (int i = 0; i < 4; i++) {
        float* dst = g_h + (size_t)(m0 + ty * 4 + i) * OUTD + tx * 8;
#pragma unroll
        for (int j = 0; j < 4; j++) {
            unsigned long long b2 = *(const unsigned long long*)&bsh[tx * 8 + 2 * j];
            unsigned long long r;
            ADD2(r, acc[i][j], b2);
            *(unsigned long long*)(dst + 2 * j) = r;
        }
    }
}

// ===== K2: a2 = h @ a2_w ; w = exp(a2 - 4); build B = [w*h | w | 0]^T fp16 K-major =====
__global__ void __launch_bounds__(256) prep_kernel(const float* __restrict__ a2w) {
    __shared__ __align__(16) float aw[128];
    __shared__ __align__(16) __half shB[BNG][64];
    const int tid = threadIdx.x;
    const int k0 = blockIdx.x * 64;
    if (tid < 128) aw[tid] = a2w[tid];
    __syncthreads();

    const int r = tid >> 2, q = tid & 3;
    const float* hrow = g_h + (size_t)(k0 + r) * OUTD + q * 32;
    float hv[32];
    float dot = 0.f;
#pragma unroll
    for (int i = 0; i < 8; i++) {
        float4 f = ((const float4*)hrow)[i];
        hv[4 * i + 0] = f.x; hv[4 * i + 1] = f.y; hv[4 * i + 2] = f.z; hv[4 * i + 3] = f.w;
        const float* ap = &aw[q * 32 + 4 * i];
        dot += f.x * ap[0] + f.y * ap[1] + f.z * ap[2] + f.w * ap[3];
    }
    dot += __shfl_xor_sync(0xFFFFFFFF, dot, 1);
    dot += __shfl_xor_sync(0xFFFFFFFF, dot, 2);
    float w = __expf(dot - 4.0f);
#pragma unroll
    for (int i = 0; i < 32; i++) shB[q * 32 + i][r] = __float2half(w * hv[i]);
    if (q == 0) shB[128][r] = __float2half(w);
    for (int idx = tid; idx < 15 * 32; idx += 256)
        ((uint32_t*)&shB[129][0])[idx] = 0u;
    __syncthreads();

    for (int idx = tid; idx < BNG * 8; idx += 256) {
        int n = idx >> 3, s = idx & 7;
        *(int4*)(g_whT + (size_t)n * NN + k0 + s * 8) = *(const int4*)&shB[n][s * 8];
    }
}

// ================= K3: out = (adj16 @ B^T)[:, :128] / col128, HMMA =================
// CTA: M=64 rows, N=144 cols, K-chunk 64. 128 threads = 4 warps (2M x 2N).
// Warp tile: 32 rows x 72 cols = 2 mtiles x 9 ntiles of m16n8k16.
// smem pitch 144B (64 halves + 8 pad) => conflict-free fragment LDS.
#define APITCH 144
#define ABUF   (64 * APITCH)      // 9216
#define BBUF   (BNG * APITCH)     // 20736

__global__ void __launch_bounds__(128) gat_kernel(const int* __restrict__ adj,
                                                  float* __restrict__ out) {
    extern __shared__ char dsm[];
    __shared__ float s_den[64];
    char* Ab[2] = { dsm, dsm + ABUF };
    char* Bb[2] = { dsm + 2 * ABUF, dsm + 2 * ABUF + BBUF };

    const int tid = threadIdx.x, lane = tid & 31, wid = tid >> 5;
    const int wm = wid & 1, wn = wid >> 1;       // M-half, N-half
    const int r4 = lane >> 2, c4 = (lane & 3);
    const int m0 = blockIdx.x * 64;

    float acc[2][9][4];
#pragma unroll
    for (int mt = 0; mt < 2; mt++)
#pragma unroll
        for (int nt = 0; nt < 9; nt++)
#pragma unroll
            for (int j = 0; j < 4; j++) acc[mt][nt][j] = 0.f;

    int4 st[4][2];

    // ---- prologue: chunk 0 ----
    {
        const int k0 = 0;
        uint32_t bb = smem_u32(Bb[0]);
#pragma unroll
        for (int i = 0; i < 9; i++) {
            int task = tid + 128 * i;
            int n = task >> 3, s = task & 7;
            cp_async16(bb + n * APITCH + s * 16, g_whT + (size_t)n * NN + k0 + s * 8);
        }
        asm volatile("cp.async.commit_group;" ::: "memory");
        uint32_t ab = smem_u32(Ab[0]);
#pragma unroll
        for (int i = 0; i < 4; i++) {
            int task = tid + 128 * i;
            int row = task >> 3, s = task & 7;
            const int4* p = (const int4*)(adj + (size_t)(m0 + row) * NN + k0 + s * 8);
            st[i][0] = ldg_cs(p);
            st[i][1] = ldg_cs(p + 1);
            uint32_t p0 = (uint32_t)st[i][0].x * 0x3C00u + (uint32_t)st[i][0].y * 0x3C000000u;
            uint32_t p1 = (uint32_t)st[i][0].z * 0x3C00u + (uint32_t)st[i][0].w * 0x3C000000u;
            uint32_t p2 = (uint32_t)st[i][1].x * 0x3C00u + (uint32_t)st[i][1].y * 0x3C000000u;
            uint32_t p3 = (uint32_t)st[i][1].z * 0x3C00u + (uint32_t)st[i][1].w * 0x3C000000u;
            sts128(ab + row * APITCH + s * 16, p0, p1, p2, p3);
        }
        asm volatile("cp.async.wait_group 0;" ::: "memory");
        __syncthreads();
    }

    // ---- main loop ----
    for (int c = 0; c < NCHUNK; c++) {
        const int cur = c & 1;

        if (c + 1 < NCHUNK) {
            const int k0 = (c + 1) * 64;
            uint32_t bb = smem_u32(Bb[cur ^ 1]);
#pragma unroll
            for (int i = 0; i < 9; i++) {
                int task = tid + 128 * i;
                int n = task >> 3, s = task & 7;
                cp_async16(bb + n * APITCH + s * 16, g_whT + (size_t)n * NN + k0 + s * 8);
            }
            asm volatile("cp.async.commit_group;" ::: "memory");
#pragma unroll
            for (int i = 0; i < 4; i++) {
                int task = tid + 128 * i;
                int row = task >> 3, s = task & 7;
                const int4* p = (const int4*)(adj + (size_t)(m0 + row) * NN + k0 + s * 8);
                st[i][0] = ldg_cs(p);
                st[i][1] = ldg_cs(p + 1);
            }
        }

        // ---- compute chunk c ----
        {
            const uint32_t as = smem_u32(Ab[cur]);
            const uint32_t bs = smem_u32(Bb[cur]);
            const uint32_t arow = as + (wm * 32 + r4) * APITCH;
            const uint32_t brow = bs + (wn * 72 + r4) * APITCH;
#pragma unroll
            for (int ks = 0; ks < 4; ks++) {
                const uint32_t koff = ks * 32 + c4 * 4;
                uint32_t bf[9][2];
#pragma unroll
                for (int nt = 0; nt < 9; nt++) {
                    uint32_t a = brow + nt * 8 * APITCH + koff;
                    bf[nt][0] = lds32(a);
                    bf[nt][1] = lds32(a + 16);
                }
                uint32_t af[2][4];
#pragma unroll
                for (int mt = 0; mt < 2; mt++) {
                    uint32_t a = arow + mt * 16 * APITCH + koff;
                    af[mt][0] = lds32(a);
                    af[mt][1] = lds32(a + 8 * APITCH);
                    af[mt][2] = lds32(a + 16);
                    af[mt][3] = lds32(a + 8 * APITCH + 16);
                }
#pragma unroll
                for (int mt = 0; mt < 2; mt++)
#pragma unroll
                    for (int nt = 0; nt < 9; nt++)
                        mma16816(acc[mt][nt], af[mt], bf[nt]);
            }
        }

        if (c + 1 < NCHUNK) {
            uint32_t ab = smem_u32(Ab[cur ^ 1]);
#pragma unroll
            for (int i = 0; i < 4; i++) {
                int task = tid + 128 * i;
                int row = task >> 3, s = task & 7;
                uint32_t p0 = (uint32_t)st[i][0].x * 0x3C00u + (uint32_t)st[i][0].y * 0x3C000000u;
                uint32_t p1 = (uint32_t)st[i][0].z * 0x3C00u + (uint32_t)st[i][0].w * 0x3C000000u;
                uint32_t p2 = (uint32_t)st[i][1].x * 0x3C00u + (uint32_t)st[i][1].y * 0x3C000000u;
                uint32_t p3 = (uint32_t)st[i][1].z * 0x3C00u + (uint32_t)st[i][1].w * 0x3C000000u;
                sts128(ab + row * APITCH + s * 16, p0, p1, p2, p3);
            }
            asm volatile("cp.async.wait_group 0;" ::: "memory");
        }
        __syncthreads();
    }

    // ---- epilogue: denominator broadcast, divide, store ----
    if (wn == 1 && (lane & 3) == 0) {
        // col 128 = local ntile 7, col offset 0
#pragma unroll
        for (int mt = 0; mt < 2; mt++) {
            s_den[wm * 32 + mt * 16 + r4]     = acc[mt][7][0];
            s_den[wm * 32 + mt * 16 + r4 + 8] = acc[mt][7][2];
        }
    }
    __syncthreads();

    const int ntmax = (wn == 1) ? 7 : 9;
#pragma unroll
    for (int mt = 0; mt < 2; mt++) {
        const int row0 = wm * 32 + mt * 16 + r4;
        const float rcp0 = 1.0f / s_den[row0];
        const float rcp1 = 1.0f / s_den[row0 + 8];
        float* o0 = out + (size_t)(m0 + row0) * OUTD;
        float* o1 = out + (size_t)(m0 + row0 + 8) * OUTD;
#pragma unroll
        for (int nt = 0; nt < 9; nt++) {
            if (nt >= ntmax) break;
            const int col = wn * 72 + nt * 8 + c4 * 2;
            float2 v0 = { acc[mt][nt][0] * rcp0, acc[mt][nt][1] * rcp0 };
            float2 v1 = { acc[mt][nt][2] * rcp1, acc[mt][nt][3] * rcp1 };
            *(float2*)(o0 + col) = v0;
            *(float2*)(o1 + col) = v1;
        }
    }
}

// ================= host =================
extern "C" void kernel_launch(void* const* d_in, const int* in_sizes, int n_in,
                              void* d_out, int out_size) {
    const float* feat = (const float*)d_in[0];
    const int*   adj  = (const int*)d_in[1];
    const float* W    = (const float*)d_in[2];
    const float* b    = (const float*)d_in[3];
    const float* a2w  = (const float*)d_in[6];
    float* out = (float*)d_out;

    proj_kernel<<<NN / 64, 256>>>(feat, W, b);
    prep_kernel<<<NN / 64, 256>>>(a2w);

    const int smem = 2 * ABUF + 2 * BBUF;   // 59904 bytes
    cudaFuncSetAttribute(gat_kernel, cudaFuncAttributeMaxDynamicSharedMemorySize, smem);
    gat_kernel<<<NN / 64, 128, smem>>>(adj, out);
}